// round 5
// baseline (speedup 1.0000x reference)
#include <cuda_runtime.h>
#include <math.h>

#define S_LEN 20
#define U_LEN 256
#define NTOK  5120
#define NC    64
#define CANDN 1024
#define HD    128
#define TOPK  10
#define RHO_C 0.02f
#define VGS   24
#define CHUNK 16
#define NWORK_MAX 384

// -------- device scratch --------
__device__ float g_vg[NC * CANDN * VGS];
__device__ float g_a[NTOK * VGS];
__device__ int   g_cnt[NC];
__device__ int   g_tok[NC * NTOK];
__device__ int2  g_work[NWORK_MAX + 32];
__device__ int   g_nwork;

// -------- constant weights --------
__constant__ float cWs1[4000];
__constant__ float cbs1[40];
__constant__ float cWs2[800];
__constant__ float cbs2[20];
__constant__ float cWt1[1600];
__constant__ float cbt1[40];
__constant__ float cWt2[800];
__constant__ float cbt2[20];
__constant__ float cWi1[1600];
__constant__ float cbi1[40];
__constant__ float cWi2[800];
__constant__ float cbi2[20];
__constant__ float cte[80];

// f32x2 helpers
__device__ __forceinline__ unsigned long long f2mul(unsigned long long a, unsigned long long b) {
    unsigned long long d;
    asm("mul.rn.f32x2 %0, %1, %2;" : "=l"(d) : "l"(a), "l"(b));
    return d;
}
__device__ __forceinline__ unsigned long long f2fma(unsigned long long a, unsigned long long b, unsigned long long c) {
    unsigned long long d;
    asm("fma.rn.f32x2 %0, %1, %2, %3;" : "=l"(d) : "l"(a), "l"(b), "l"(c));
    return d;
}
__device__ __forceinline__ unsigned long long f2add(unsigned long long a, unsigned long long b) {
    unsigned long long d;
    asm("add.rn.f32x2 %0, %1, %2;" : "=l"(d) : "l"(a), "l"(b));
    return d;
}

// ============ K_mid: cand MLP (0..127) | token MLP (128..147) | bucket (148) ============
__global__ void k_mid(const int* __restrict__ x, const int* __restrict__ tslot,
                      const float* __restrict__ vecs, const int* __restrict__ cand,
                      const int* __restrict__ Iarr) {
    int b = blockIdx.x, tid = threadIdx.x;

    if (b < 128) {
        // ---- candidate-side MLP: 65536 rows, 2 per thread, const weights ----
        __shared__ float tcs[40];   // b_ti1 + te[2] @ W_ti1[20:]
        if (tid < 40) {
            float acc = cbi1[tid];
            #pragma unroll
            for (int i = 0; i < 20; i++) acc += cte[40 + i] * cWi1[(20 + i) * 40 + tid];
            tcs[tid] = acc;
        }
        __syncthreads();

        int g0 = b * 512 + tid;
        int v0 = cand[g0], v1 = cand[g0 + 256];
        float in0[20], in1[20];
        const float4* p0 = (const float4*)(vecs + (size_t)v0 * 20);
        const float4* p1 = (const float4*)(vecs + (size_t)v1 * 20);
        #pragma unroll
        for (int q = 0; q < 5; q++) {
            float4 f = p0[q];
            in0[4*q] = f.x; in0[4*q+1] = f.y; in0[4*q+2] = f.z; in0[4*q+3] = f.w;
            float4 h = p1[q];
            in1[4*q] = h.x; in1[4*q+1] = h.y; in1[4*q+2] = h.z; in1[4*q+3] = h.w;
        }
        float o0[20], o1[20];
        #pragma unroll
        for (int d = 0; d < 20; d++) { o0[d] = cbi2[d]; o1[d] = cbi2[d]; }
        #pragma unroll 2
        for (int a = 0; a < 40; a++) {
            float h0 = tcs[a], h1 = h0;
            #pragma unroll
            for (int i = 0; i < 20; i++) {
                float w = cWi1[i * 40 + a];
                h0 += in0[i] * w; h1 += in1[i] * w;
            }
            h0 = fmaxf(h0, 0.0f); h1 = fmaxf(h1, 0.0f);
            #pragma unroll
            for (int d = 0; d < 20; d++) {
                float w = cWi2[a * 20 + d];
                o0[d] += h0 * w; o1[d] += h1 * w;
            }
        }
        float n0 = 0.0f, n1 = 0.0f;
        float* d0 = g_vg + (size_t)g0 * VGS;
        float* d1 = g_vg + (size_t)(g0 + 256) * VGS;
        #pragma unroll
        for (int d = 0; d < 20; d++) {
            n0 += o0[d] * o0[d]; d0[d] = o0[d];
            n1 += o1[d] * o1[d]; d1[d] = o1[d];
        }
        d0[20] = n0; d0[21] = 1.0f;
        d1[20] = n1; d1[21] = 1.0f;

    } else if (b < 148) {
        // ---- token MLP: 1 thread/token, const weights ----
        __shared__ float tcs2[120];  // b_to1 + te[s] @ W_to1[20:]
        if (tid < 120) {
            int s = tid / 40, a = tid % 40;
            float acc = cbt1[a];
            #pragma unroll
            for (int i = 0; i < 20; i++) acc += cte[s * 20 + i] * cWt1[(20 + i) * 40 + a];
            tcs2[tid] = acc;
        }
        __syncthreads();

        int n = (b - 128) * 256 + tid;
        int s = n / U_LEN, u = n % U_LEN;

        float hseq[40];
        #pragma unroll
        for (int a = 0; a < 40; a++) hseq[a] = cbs1[a];

        float e[20];
        #pragma unroll 1
        for (int p = 0; p < 5; p++) {
            int k = 4 - p;
            int sel = (s < k) ? s : s - k;
            int xid = x[sel * U_LEN + u];
            const float4* vp = (const float4*)(vecs + (size_t)xid * 20);
            #pragma unroll
            for (int q = 0; q < 5; q++) {
                float4 f = vp[q];
                e[4*q] = f.x; e[4*q+1] = f.y; e[4*q+2] = f.z; e[4*q+3] = f.w;
            }
            #pragma unroll
            for (int i = 0; i < 20; i++) {
                float ei = e[i];
                #pragma unroll
                for (int a = 0; a < 40; a++) hseq[a] += ei * cWs1[(p * 20 + i) * 40 + a];
            }
        }

        float ho[20];
        #pragma unroll
        for (int d = 0; d < 20; d++) ho[d] = cbs2[d];
        #pragma unroll 2
        for (int a = 0; a < 40; a++) {
            float r = fmaxf(hseq[a], 0.0f);
            #pragma unroll
            for (int d = 0; d < 20; d++) ho[d] += r * cWs2[a * 20 + d];
        }

        int t24 = tslot[n] % 24;
        int seg = (t24 >= 22 || t24 < 6) ? 0 : (t24 < 14 ? 1 : 2);
        float hto[40];
        #pragma unroll
        for (int a = 0; a < 40; a++) hto[a] = tcs2[seg * 40 + a];
        #pragma unroll
        for (int i = 0; i < 20; i++) {
            float ei = e[i];
            #pragma unroll
            for (int a = 0; a < 40; a++) hto[a] += ei * cWt1[i * 40 + a];
        }
        float xo[20];
        #pragma unroll
        for (int d = 0; d < 20; d++) xo[d] = cbt2[d];
        #pragma unroll 2
        for (int a = 0; a < 40; a++) {
            float r = fmaxf(hto[a], 0.0f);
            #pragma unroll
            for (int d = 0; d < 20; d++) xo[d] += r * cWt2[a * 20 + d];
        }

        float nrm = 0.0f;
        float* dst = g_a + (size_t)n * VGS;
        #pragma unroll
        for (int d = 0; d < 20; d++) {
            float av = 0.5f * (ho[d] + xo[d]);
            dst[d] = av; nrm += av * av;
        }
        dst[20] = -0.5f;
        dst[21] = -0.5f * nrm;

    } else {
        // ---- bucket tokens + worklist; gathers prefetched (breaks dep chain) ----
        __shared__ int scnt[NC];
        if (tid < NC) scnt[tid] = 0;
        __syncthreads();
        int xv[20];
        #pragma unroll
        for (int q = 0; q < 20; q++) xv[q] = x[tid + 256 * q];
        int cv[20];
        #pragma unroll
        for (int q = 0; q < 20; q++) cv[q] = Iarr[xv[q]];
        #pragma unroll
        for (int q = 0; q < 20; q++) {
            int c = cv[q];
            int p = atomicAdd(&scnt[c], 1);
            g_tok[c * NTOK + p] = tid + 256 * q;
        }
        __syncthreads();
        if (tid < NC) g_cnt[tid] = scnt[tid];
        if (tid == 0) {
            int w = 0;
            for (int c = 0; c < NC; c++) {
                int cnt = scnt[c];
                for (int st = 0; st < cnt; st += CHUNK) g_work[w++] = make_int2(c, st);
            }
            g_nwork = w;
        }
    }
}

// ============ K3: 16 tokens/block, 64 cands/lane, folded-norm dot, occ=3 ============
__global__ void __launch_bounds__(256, 3)
k3_score(const int* __restrict__ x, const int* __restrict__ cand,
         const float* __restrict__ Eemb, float* __restrict__ out) {
    int bid = blockIdx.x;
    if (bid >= g_nwork) return;
    int2 wk = g_work[bid];
    int cid = wk.x, start = wk.y;
    int cnt = g_cnt[cid];
    int nIn = min(CHUNK, cnt - start);

    int tid = threadIdx.x, lane = tid & 31, warp = tid >> 5;

    __shared__ unsigned long long part[8][32][TOPK];
    __shared__ float sw_s[CHUNK][12];
    __shared__ int   si_s[CHUNK][12];
    __shared__ int   tok_s[CHUNK];

    if (tid < CHUNK) tok_s[tid] = g_tok[cid * NTOK + start + min(tid, nIn - 1)];
    __syncthreads();

    int tl = lane & 15;
    int half = lane >> 4;
    int token = tok_s[tl];

    const float* ap = g_a + (size_t)token * VGS;
    const ulonglong2* apv = (const ulonglong2*)ap;
    ulonglong2 A0 = apv[0], A1 = apv[1], A2 = apv[2], A3 = apv[3], A4 = apv[4];
    unsigned long long A5 = *(const unsigned long long*)(ap + 20);

    const float* vg = g_vg + (size_t)(cid * CANDN) * VGS;
    int j0 = warp * 128 + half * 64;

    float tv[TOPK]; int tj[TOPK];
    #pragma unroll
    for (int q = 0; q < TOPK; q++) { tv[q] = 3.4e38f; tj[q] = 0; }

    #pragma unroll 2
    for (int jj = 0; jj < 64; jj++) {
        int j = j0 + jj;
        const float* vp = vg + (size_t)j * VGS;
        const ulonglong2* vp2 = (const ulonglong2*)vp;
        ulonglong2 q0 = vp2[0], q1 = vp2[1], q2 = vp2[2], q3 = vp2[3], q4 = vp2[4];
        unsigned long long q5 = *(const unsigned long long*)(vp + 20);
        unsigned long long s0 = f2mul(q0.x, A0.x);
        unsigned long long s1 = f2mul(q0.y, A0.y);
        s0 = f2fma(q1.x, A1.x, s0); s1 = f2fma(q1.y, A1.y, s1);
        s0 = f2fma(q2.x, A2.x, s0); s1 = f2fma(q2.y, A2.y, s1);
        s0 = f2fma(q3.x, A3.x, s0); s1 = f2fma(q3.y, A3.y, s1);
        s0 = f2fma(q4.x, A4.x, s0); s1 = f2fma(q4.y, A4.y, s1);
        s0 = f2fma(q5, A5, s0);
        s0 = f2add(s0, s1);
        float lo = __uint_as_float((unsigned)(s0 & 0xffffffffull));
        float hi = __uint_as_float((unsigned)(s0 >> 32));
        float d2 = fmaxf(-2.0f * (lo + hi), 1e-12f);
        if (d2 < tv[TOPK - 1]) {
            float cv2 = d2; int cj = j;
            #pragma unroll
            for (int q = 0; q < TOPK; q++) {
                bool p = cv2 < tv[q];
                float nv = p ? cv2 : tv[q];
                float xv = p ? tv[q] : cv2;
                int   nj = p ? cj : tj[q];
                int   xj = p ? tj[q] : cj;
                tv[q] = nv; tj[q] = nj; cv2 = xv; cj = xj;
            }
        }
    }
    #pragma unroll
    for (int q = 0; q < TOPK; q++)
        part[warp][lane][q] =
            ((unsigned long long)__float_as_uint(tv[q]) << 32) | (unsigned)tj[q];
    __syncthreads();

    // ---- 16-way streaming merge per token + softmax weights ----
    if (tid < nIn) {
        int t = tid;
        unsigned long long h[16];
        int p[16];
        #pragma unroll
        for (int w = 0; w < 8; w++) {
            h[w]     = part[w][t][0];      p[w] = 1;
            h[8 + w] = part[w][16 + t][0]; p[8 + w] = 1;
        }
        float ssum = 1.0f;
        #pragma unroll
        for (int k = 0; k < TOPK; k++) {
            unsigned long long best = h[0]; int bw = 0;
            #pragma unroll
            for (int l = 1; l < 16; l++) if (h[l] < best) { best = h[l]; bw = l; }
            #pragma unroll
            for (int l = 0; l < 16; l++) {
                if (bw == l) {
                    int tl2 = (l < 8) ? t : 16 + t;
                    int wq  = (l < 8) ? l : l - 8;
                    h[l] = (p[l] < TOPK) ? part[wq][tl2][p[l]] : 0xFFFFFFFFFFFFFFFFull;
                    p[l]++;
                }
            }
            float d2 = __uint_as_float((unsigned)(best >> 32));
            int   j  = (int)(best & 0xffffffffu);
            float sc = expf(-RHO_C * sqrtf(d2));
            float e  = expf(sc - 1.0f);
            ssum += e;
            sw_s[t][k] = e;
            si_s[t][k] = cand[cid * CANDN + j];
        }
        sw_s[t][TOPK] = 1.0f;
        si_s[t][TOPK] = x[tok_s[t]];
        float inv = 1.0f / ssum;
        #pragma unroll
        for (int k = 0; k < 11; k++) sw_s[t][k] *= inv;
    }
    __syncthreads();

    // ---- weighted embedding gather: 16 threads/token, 8 floats each ----
    int t  = tid >> 4;
    int pg = tid & 15;
    if (t < nIn) {
        int token2 = tok_s[t];
        float4 a0 = make_float4(0.f, 0.f, 0.f, 0.f), a1 = a0;
        #pragma unroll
        for (int k = 0; k < 11; k++) {
            float w = sw_s[t][k];
            const float4* ep = (const float4*)(Eemb + (size_t)si_s[t][k] * HD + pg * 8);
            float4 e0 = ep[0], e1 = ep[1];
            a0.x += w * e0.x; a0.y += w * e0.y; a0.z += w * e0.z; a0.w += w * e0.w;
            a1.x += w * e1.x; a1.y += w * e1.y; a1.z += w * e1.z; a1.w += w * e1.w;
        }
        float4* op = (float4*)(out + (size_t)token2 * HD + pg * 8);
        op[0] = a0; op[1] = a1;
    }
}

// ============ launch ============
extern "C" void kernel_launch(void* const* d_in, const int* in_sizes, int n_in,
                              void* d_out, int out_size) {
    const int*   x     = (const int*)  d_in[0];
    const int*   tslot = (const int*)  d_in[1];
    const float* vecs  = (const float*)d_in[2];
    const float* Eemb  = (const float*)d_in[3];
    const int*   Iarr  = (const int*)  d_in[4];
    const int*   cand  = (const int*)  d_in[5];
    float* out = (float*)d_out;

    cudaMemcpyToSymbolAsync(cte,  d_in[6],  80 * 4,  0, cudaMemcpyDeviceToDevice);
    cudaMemcpyToSymbolAsync(cWs1, d_in[7], 4000 * 4, 0, cudaMemcpyDeviceToDevice);
    cudaMemcpyToSymbolAsync(cbs1, d_in[8],  40 * 4,  0, cudaMemcpyDeviceToDevice);
    cudaMemcpyToSymbolAsync(cWs2, d_in[9],  800 * 4, 0, cudaMemcpyDeviceToDevice);
    cudaMemcpyToSymbolAsync(cbs2, d_in[10], 20 * 4,  0, cudaMemcpyDeviceToDevice);
    cudaMemcpyToSymbolAsync(cWt1, d_in[11], 1600 * 4, 0, cudaMemcpyDeviceToDevice);
    cudaMemcpyToSymbolAsync(cbt1, d_in[12], 40 * 4,  0, cudaMemcpyDeviceToDevice);
    cudaMemcpyToSymbolAsync(cWt2, d_in[13], 800 * 4, 0, cudaMemcpyDeviceToDevice);
    cudaMemcpyToSymbolAsync(cbt2, d_in[14], 20 * 4,  0, cudaMemcpyDeviceToDevice);
    cudaMemcpyToSymbolAsync(cWi1, d_in[15], 1600 * 4, 0, cudaMemcpyDeviceToDevice);
    cudaMemcpyToSymbolAsync(cbi1, d_in[16], 40 * 4,  0, cudaMemcpyDeviceToDevice);
    cudaMemcpyToSymbolAsync(cWi2, d_in[17], 800 * 4, 0, cudaMemcpyDeviceToDevice);
    cudaMemcpyToSymbolAsync(cbi2, d_in[18], 20 * 4,  0, cudaMemcpyDeviceToDevice);

    k_mid<<<149, 256>>>(x, tslot, vecs, cand, Iarr);
    k3_score<<<NWORK_MAX, 256>>>(x, cand, Eemb, out);
}

// round 6
// speedup vs baseline: 1.3373x; 1.3373x over previous
#include <cuda_runtime.h>
#include <math.h>

#define S_LEN 20
#define U_LEN 256
#define NTOK  5120
#define NC    64
#define CANDN 1024
#define HD    128
#define TOPK  10
#define RHO_C 0.02f
#define VGS   24
#define CHUNK 16
#define NWORK_MAX 384

// -------- device scratch --------
__device__ float g_vg[NC * CANDN * VGS];
__device__ float g_a[NTOK * VGS];
__device__ int   g_cnt[NC];
__device__ int   g_tok[NC * NTOK];
__device__ int2  g_work[NWORK_MAX + 32];
__device__ int   g_nwork;

// f32x2 helpers
__device__ __forceinline__ unsigned long long f2mul(unsigned long long a, unsigned long long b) {
    unsigned long long d;
    asm("mul.rn.f32x2 %0, %1, %2;" : "=l"(d) : "l"(a), "l"(b));
    return d;
}
__device__ __forceinline__ unsigned long long f2fma(unsigned long long a, unsigned long long b, unsigned long long c) {
    unsigned long long d;
    asm("fma.rn.f32x2 %0, %1, %2, %3;" : "=l"(d) : "l"(a), "l"(b), "l"(c));
    return d;
}
__device__ __forceinline__ unsigned long long f2add(unsigned long long a, unsigned long long b) {
    unsigned long long d;
    asm("add.rn.f32x2 %0, %1, %2;" : "=l"(d) : "l"(a), "l"(b));
    return d;
}

// ============ K_mid, 128-thread blocks:
//   b<512   : candidate MLP, 1 row/thread (65536 rows)
//   b<552   : token MLP, 1 token/thread (5120 tokens)
//   b==552  : bucket + worklist
__global__ void k_mid(const int* __restrict__ x, const int* __restrict__ tslot,
                      const float* __restrict__ vecs, const int* __restrict__ cand,
                      const int* __restrict__ Iarr, const float* __restrict__ te,
                      const float* __restrict__ Wseq1, const float* __restrict__ bseq1,
                      const float* __restrict__ Wseq2, const float* __restrict__ bseq2,
                      const float* __restrict__ Wto1, const float* __restrict__ bto1,
                      const float* __restrict__ Wto2, const float* __restrict__ bto2,
                      const float* __restrict__ Wti1, const float* __restrict__ bti1,
                      const float* __restrict__ Wti2, const float* __restrict__ bti2) {
    __shared__ float sb[6600];
    int b = blockIdx.x, tid = threadIdx.x;

    if (b < 512) {
        // ---- candidate-side MLP ----
        float* W1s = sb;            // 800
        float* W2s = sb + 800;      // 800
        float* tcs = sb + 1600;     // 40
        float* b2s = sb + 1640;     // 20
        for (int i = tid; i < 800; i += 128) { W1s[i] = Wti1[i]; W2s[i] = Wti2[i]; }
        if (tid < 40) {
            float acc = bti1[tid];
            #pragma unroll
            for (int i = 0; i < 20; i++) acc += te[40 + i] * Wti1[(20 + i) * 40 + tid];
            tcs[tid] = acc;
        }
        if (tid >= 64 && tid < 84) b2s[tid - 64] = bti2[tid - 64];
        __syncthreads();

        int g = b * 128 + tid;
        int v = cand[g];
        float in[20];
        const float4* vp = (const float4*)(vecs + (size_t)v * 20);
        #pragma unroll
        for (int q = 0; q < 5; q++) {
            float4 f = vp[q];
            in[4*q] = f.x; in[4*q+1] = f.y; in[4*q+2] = f.z; in[4*q+3] = f.w;
        }
        float o[20];
        #pragma unroll
        for (int d = 0; d < 20; d++) o[d] = b2s[d];
        #pragma unroll 4
        for (int a = 0; a < 40; a++) {
            float h = tcs[a];
            #pragma unroll
            for (int i = 0; i < 20; i++) h += in[i] * W1s[i * 40 + a];
            h = fmaxf(h, 0.0f);
            #pragma unroll
            for (int d = 0; d < 20; d++) o[d] += h * W2s[a * 20 + d];
        }
        float nrm = 0.0f;
        float* dst = g_vg + (size_t)g * VGS;
        #pragma unroll
        for (int d = 0; d < 20; d++) { nrm += o[d] * o[d]; dst[d] = o[d]; }
        dst[20] = nrm;
        dst[21] = 1.0f;

    } else if (b < 552) {
        // ---- token MLP ----
        float* Ws1 = sb;            // 4000
        float* Ws2 = sb + 4000;     // 800
        float* Wt1 = sb + 4800;     // 800
        float* Wt2 = sb + 5600;     // 800
        __shared__ float bs1[40], bs2[20], bt2s[20], tcs2[120];
        for (int i = tid; i < 4000; i += 128) Ws1[i] = Wseq1[i];
        for (int i = tid; i < 800; i += 128) { Ws2[i] = Wseq2[i]; Wt1[i] = Wto1[i]; Wt2[i] = Wto2[i]; }
        if (tid < 40) bs1[tid] = bseq1[tid];
        if (tid >= 64 && tid < 84) { bs2[tid - 64] = bseq2[tid - 64]; bt2s[tid - 64] = bto2[tid - 64]; }
        __syncthreads();
        if (tid < 120) {
            int s = tid / 40, a = tid % 40;
            float acc = bto1[a];
            #pragma unroll
            for (int i = 0; i < 20; i++) acc += te[s * 20 + i] * Wto1[(20 + i) * 40 + a];
            tcs2[tid] = acc;
        }
        __syncthreads();

        int n = (b - 512) * 128 + tid;
        int s = n / U_LEN, u = n % U_LEN;

        float hseq[40];
        #pragma unroll
        for (int a = 0; a < 40; a++) hseq[a] = bs1[a];

        float e[20];
        #pragma unroll 1
        for (int p = 0; p < 5; p++) {
            int k = 4 - p;
            int sel = (s < k) ? s : s - k;
            int xid = x[sel * U_LEN + u];
            const float4* vp = (const float4*)(vecs + (size_t)xid * 20);
            #pragma unroll
            for (int q = 0; q < 5; q++) {
                float4 f = vp[q];
                e[4*q] = f.x; e[4*q+1] = f.y; e[4*q+2] = f.z; e[4*q+3] = f.w;
            }
            #pragma unroll
            for (int i = 0; i < 20; i++) {
                float ei = e[i];
                #pragma unroll
                for (int a = 0; a < 40; a++) hseq[a] += ei * Ws1[(p * 20 + i) * 40 + a];
            }
        }

        float ho[20];
        #pragma unroll
        for (int d = 0; d < 20; d++) ho[d] = bs2[d];
        #pragma unroll 4
        for (int a = 0; a < 40; a++) {
            float r = fmaxf(hseq[a], 0.0f);
            #pragma unroll
            for (int d = 0; d < 20; d++) ho[d] += r * Ws2[a * 20 + d];
        }

        int t24 = tslot[n] % 24;
        int seg = (t24 >= 22 || t24 < 6) ? 0 : (t24 < 14 ? 1 : 2);
        float hto[40];
        #pragma unroll
        for (int a = 0; a < 40; a++) hto[a] = tcs2[seg * 40 + a];
        #pragma unroll
        for (int i = 0; i < 20; i++) {
            float ei = e[i];
            #pragma unroll
            for (int a = 0; a < 40; a++) hto[a] += ei * Wt1[i * 40 + a];
        }
        float xo[20];
        #pragma unroll
        for (int d = 0; d < 20; d++) xo[d] = bt2s[d];
        #pragma unroll 4
        for (int a = 0; a < 40; a++) {
            float r = fmaxf(hto[a], 0.0f);
            #pragma unroll
            for (int d = 0; d < 20; d++) xo[d] += r * Wt2[a * 20 + d];
        }

        float nrm = 0.0f;
        float* dst = g_a + (size_t)n * VGS;
        #pragma unroll
        for (int d = 0; d < 20; d++) {
            float av = 0.5f * (ho[d] + xo[d]);
            dst[d] = av; nrm += av * av;
        }
        dst[20] = -0.5f;
        dst[21] = -0.5f * nrm;

    } else {
        // ---- bucket + worklist (prefetched gathers) ----
        __shared__ int scnt[NC];
        if (tid < NC) scnt[tid] = 0;
        __syncthreads();
        int xv[40];
        #pragma unroll
        for (int q = 0; q < 40; q++) xv[q] = x[tid + 128 * q];
        int cv[40];
        #pragma unroll
        for (int q = 0; q < 40; q++) cv[q] = Iarr[xv[q]];
        #pragma unroll
        for (int q = 0; q < 40; q++) {
            int c = cv[q];
            int p = atomicAdd(&scnt[c], 1);
            g_tok[c * NTOK + p] = tid + 128 * q;
        }
        __syncthreads();
        if (tid < NC) g_cnt[tid] = scnt[tid];
        if (tid == 0) {
            int w = 0;
            for (int c = 0; c < NC; c++) {
                int cnt = scnt[c];
                for (int st = 0; st < cnt; st += CHUNK) g_work[w++] = make_int2(c, st);
            }
            g_nwork = w;
        }
    }
}

// ============ K3: 16 tokens/block, 64 cands/lane, 4-chain dot, occ=3 ============
__global__ void __launch_bounds__(256, 3)
k3_score(const int* __restrict__ x, const int* __restrict__ cand,
         const float* __restrict__ Eemb, float* __restrict__ out) {
    int bid = blockIdx.x;
    if (bid >= g_nwork) return;
    int2 wk = g_work[bid];
    int cid = wk.x, start = wk.y;
    int cnt = g_cnt[cid];
    int nIn = min(CHUNK, cnt - start);

    int tid = threadIdx.x, lane = tid & 31, warp = tid >> 5;

    __shared__ unsigned long long part[8][32][TOPK];
    __shared__ float sw_s[CHUNK][12];
    __shared__ int   si_s[CHUNK][12];
    __shared__ int   tok_s[CHUNK];

    if (tid < CHUNK) tok_s[tid] = g_tok[cid * NTOK + start + min(tid, nIn - 1)];
    __syncthreads();

    int tl = lane & 15;
    int half = lane >> 4;
    int token = tok_s[tl];

    const float* ap = g_a + (size_t)token * VGS;
    const ulonglong2* apv = (const ulonglong2*)ap;
    ulonglong2 A0 = apv[0], A1 = apv[1], A2 = apv[2], A3 = apv[3], A4 = apv[4];
    unsigned long long A5 = *(const unsigned long long*)(ap + 20);

    const float* vg = g_vg + (size_t)(cid * CANDN) * VGS;
    int j0 = warp * 128 + half * 64;

    float tv[TOPK]; int tj[TOPK];
    #pragma unroll
    for (int q = 0; q < TOPK; q++) { tv[q] = 3.4e38f; tj[q] = 0; }

    #pragma unroll 2
    for (int jj = 0; jj < 64; jj++) {
        int j = j0 + jj;
        const float* vp = vg + (size_t)j * VGS;
        const ulonglong2* vp2 = (const ulonglong2*)vp;
        ulonglong2 q0 = vp2[0], q1 = vp2[1], q2 = vp2[2], q3 = vp2[3], q4 = vp2[4];
        unsigned long long q5 = *(const unsigned long long*)(vp + 20);
        // 4 independent FMA chains
        unsigned long long s0 = f2mul(q0.x, A0.x);
        unsigned long long s1 = f2mul(q0.y, A0.y);
        unsigned long long s2 = f2mul(q1.x, A1.x);
        unsigned long long s3 = f2mul(q1.y, A1.y);
        s0 = f2fma(q2.x, A2.x, s0);
        s1 = f2fma(q2.y, A2.y, s1);
        s2 = f2fma(q3.x, A3.x, s2);
        s3 = f2fma(q3.y, A3.y, s3);
        s0 = f2fma(q4.x, A4.x, s0);
        s1 = f2fma(q4.y, A4.y, s1);
        s2 = f2fma(q5, A5, s2);
        s0 = f2add(s0, s1);
        s2 = f2add(s2, s3);
        s0 = f2add(s0, s2);
        float lo = __uint_as_float((unsigned)(s0 & 0xffffffffull));
        float hi = __uint_as_float((unsigned)(s0 >> 32));
        float d2 = fmaxf(-2.0f * (lo + hi), 1e-12f);
        if (d2 < tv[TOPK - 1]) {
            float cv2 = d2; int cj = j;
            #pragma unroll
            for (int q = 0; q < TOPK; q++) {
                bool p = cv2 < tv[q];
                float nv = p ? cv2 : tv[q];
                float xv = p ? tv[q] : cv2;
                int   nj = p ? cj : tj[q];
                int   xj = p ? tj[q] : cj;
                tv[q] = nv; tj[q] = nj; cv2 = xv; cj = xj;
            }
        }
    }
    #pragma unroll
    for (int q = 0; q < TOPK; q++)
        part[warp][lane][q] =
            ((unsigned long long)__float_as_uint(tv[q]) << 32) | (unsigned)tj[q];
    __syncthreads();

    // ---- 16-way streaming merge per token + softmax weights ----
    if (tid < nIn) {
        int t = tid;
        unsigned long long h[16];
        int p[16];
        #pragma unroll
        for (int w = 0; w < 8; w++) {
            h[w]     = part[w][t][0];      p[w] = 1;
            h[8 + w] = part[w][16 + t][0]; p[8 + w] = 1;
        }
        float ssum = 1.0f;
        #pragma unroll
        for (int k = 0; k < TOPK; k++) {
            unsigned long long best = h[0]; int bw = 0;
            #pragma unroll
            for (int l = 1; l < 16; l++) if (h[l] < best) { best = h[l]; bw = l; }
            #pragma unroll
            for (int l = 0; l < 16; l++) {
                if (bw == l) {
                    int tl2 = (l < 8) ? t : 16 + t;
                    int wq  = (l < 8) ? l : l - 8;
                    h[l] = (p[l] < TOPK) ? part[wq][tl2][p[l]] : 0xFFFFFFFFFFFFFFFFull;
                    p[l]++;
                }
            }
            float d2 = __uint_as_float((unsigned)(best >> 32));
            int   j  = (int)(best & 0xffffffffu);
            float sc = expf(-RHO_C * sqrtf(d2));
            float e  = expf(sc - 1.0f);
            ssum += e;
            sw_s[t][k] = e;
            si_s[t][k] = cand[cid * CANDN + j];
        }
        sw_s[t][TOPK] = 1.0f;
        si_s[t][TOPK] = x[tok_s[t]];
        float inv = 1.0f / ssum;
        #pragma unroll
        for (int k = 0; k < 11; k++) sw_s[t][k] *= inv;
    }
    __syncthreads();

    // ---- weighted embedding gather: 16 threads/token, 8 floats each ----
    int t  = tid >> 4;
    int pg = tid & 15;
    if (t < nIn) {
        int token2 = tok_s[t];
        float4 a0 = make_float4(0.f, 0.f, 0.f, 0.f), a1 = a0;
        #pragma unroll
        for (int k = 0; k < 11; k++) {
            float w = sw_s[t][k];
            const float4* ep = (const float4*)(Eemb + (size_t)si_s[t][k] * HD + pg * 8);
            float4 e0 = ep[0], e1 = ep[1];
            a0.x += w * e0.x; a0.y += w * e0.y; a0.z += w * e0.z; a0.w += w * e0.w;
            a1.x += w * e1.x; a1.y += w * e1.y; a1.z += w * e1.z; a1.w += w * e1.w;
        }
        float4* op = (float4*)(out + (size_t)token2 * HD + pg * 8);
        op[0] = a0; op[1] = a1;
    }
}

// ============ launch ============
extern "C" void kernel_launch(void* const* d_in, const int* in_sizes, int n_in,
                              void* d_out, int out_size) {
    const int*   x     = (const int*)  d_in[0];
    const int*   tslot = (const int*)  d_in[1];
    const float* vecs  = (const float*)d_in[2];
    const float* Eemb  = (const float*)d_in[3];
    const int*   Iarr  = (const int*)  d_in[4];
    const int*   cand  = (const int*)  d_in[5];
    const float* te    = (const float*)d_in[6];
    const float* Wseq1 = (const float*)d_in[7];
    const float* bseq1 = (const float*)d_in[8];
    const float* Wseq2 = (const float*)d_in[9];
    const float* bseq2 = (const float*)d_in[10];
    const float* Wto1  = (const float*)d_in[11];
    const float* bto1  = (const float*)d_in[12];
    const float* Wto2  = (const float*)d_in[13];
    const float* bto2  = (const float*)d_in[14];
    const float* Wti1  = (const float*)d_in[15];
    const float* bti1  = (const float*)d_in[16];
    const float* Wti2  = (const float*)d_in[17];
    const float* bti2  = (const float*)d_in[18];
    float* out = (float*)d_out;

    k_mid<<<553, 128>>>(x, tslot, vecs, cand, Iarr, te,
                        Wseq1, bseq1, Wseq2, bseq2,
                        Wto1, bto1, Wto2, bto2,
                        Wti1, bti1, Wti2, bti2);
    k3_score<<<NWORK_MAX, 256>>>(x, cand, Eemb, out);
}

// round 7
// speedup vs baseline: 1.6123x; 1.2056x over previous
#include <cuda_runtime.h>
#include <math.h>

#define S_LEN 20
#define U_LEN 256
#define NTOK  5120
#define NC    64
#define CANDN 1024
#define HD    128
#define TOPK  10
#define RHO_C 0.02f
#define VGS   24
#define CHUNK 16
#define NWORK_MAX 384

// -------- device scratch (g_vg padded +1 row: prefetch overrun target) --------
__device__ float g_vg[(NC * CANDN + 1) * VGS];
__device__ float g_a[NTOK * VGS];
__device__ int   g_cnt[NC];
__device__ int   g_tok[NC * NTOK];
__device__ int2  g_work[NWORK_MAX + 32];
__device__ int   g_nwork;

// f32x2 helpers
__device__ __forceinline__ unsigned long long f2mul(unsigned long long a, unsigned long long b) {
    unsigned long long d;
    asm("mul.rn.f32x2 %0, %1, %2;" : "=l"(d) : "l"(a), "l"(b));
    return d;
}
__device__ __forceinline__ unsigned long long f2fma(unsigned long long a, unsigned long long b, unsigned long long c) {
    unsigned long long d;
    asm("fma.rn.f32x2 %0, %1, %2, %3;" : "=l"(d) : "l"(a), "l"(b), "l"(c));
    return d;
}
__device__ __forceinline__ unsigned long long f2add(unsigned long long a, unsigned long long b) {
    unsigned long long d;
    asm("add.rn.f32x2 %0, %1, %2;" : "=l"(d) : "l"(a), "l"(b));
    return d;
}

// ============ K_mid, 128-thread blocks:
//   b<256   : candidate MLP, 2 rows/thread (65536 rows)
//   b<336   : token MLP, 2 threads/token (5120 tokens)
//   b==336  : bucket + worklist
__global__ void k_mid(const int* __restrict__ x, const int* __restrict__ tslot,
                      const float* __restrict__ vecs, const int* __restrict__ cand,
                      const int* __restrict__ Iarr, const float* __restrict__ te,
                      const float* __restrict__ Wseq1, const float* __restrict__ bseq1,
                      const float* __restrict__ Wseq2, const float* __restrict__ bseq2,
                      const float* __restrict__ Wto1, const float* __restrict__ bto1,
                      const float* __restrict__ Wto2, const float* __restrict__ bto2,
                      const float* __restrict__ Wti1, const float* __restrict__ bti1,
                      const float* __restrict__ Wti2, const float* __restrict__ bti2) {
    __shared__ float sb[6600];
    int b = blockIdx.x, tid = threadIdx.x;

    if (b < 256) {
        // ---- candidate-side MLP: 2 rows per thread ----
        float* W1s = sb;            // 800
        float* W2s = sb + 800;      // 800
        float* tcs = sb + 1600;     // 40
        float* b2s = sb + 1640;     // 20
        for (int i = tid; i < 800; i += 128) { W1s[i] = Wti1[i]; W2s[i] = Wti2[i]; }
        if (tid < 40) {
            float acc = bti1[tid];
            #pragma unroll
            for (int i = 0; i < 20; i++) acc += te[40 + i] * Wti1[(20 + i) * 40 + tid];
            tcs[tid] = acc;
        }
        if (tid >= 64 && tid < 84) b2s[tid - 64] = bti2[tid - 64];
        __syncthreads();

        int g0 = b * 256 + tid;
        int v0 = cand[g0], v1 = cand[g0 + 128];
        float in0[20], in1[20];
        const float4* p0 = (const float4*)(vecs + (size_t)v0 * 20);
        const float4* p1 = (const float4*)(vecs + (size_t)v1 * 20);
        #pragma unroll
        for (int q = 0; q < 5; q++) {
            float4 f = p0[q];
            in0[4*q] = f.x; in0[4*q+1] = f.y; in0[4*q+2] = f.z; in0[4*q+3] = f.w;
            float4 h = p1[q];
            in1[4*q] = h.x; in1[4*q+1] = h.y; in1[4*q+2] = h.z; in1[4*q+3] = h.w;
        }
        float o0[20], o1[20];
        #pragma unroll
        for (int d = 0; d < 20; d++) { o0[d] = b2s[d]; o1[d] = b2s[d]; }
        #pragma unroll 2
        for (int a = 0; a < 40; a++) {
            float h0 = tcs[a], h1 = h0;
            #pragma unroll
            for (int i = 0; i < 20; i++) {
                float w = W1s[i * 40 + a];
                h0 += in0[i] * w; h1 += in1[i] * w;
            }
            h0 = fmaxf(h0, 0.0f); h1 = fmaxf(h1, 0.0f);
            #pragma unroll
            for (int d = 0; d < 20; d++) {
                float w = W2s[a * 20 + d];
                o0[d] += h0 * w; o1[d] += h1 * w;
            }
        }
        float n0 = 0.0f, n1 = 0.0f;
        float* d0 = g_vg + (size_t)g0 * VGS;
        float* d1 = g_vg + (size_t)(g0 + 128) * VGS;
        #pragma unroll
        for (int d = 0; d < 20; d++) {
            n0 += o0[d] * o0[d]; d0[d] = o0[d];
            n1 += o1[d] * o1[d]; d1[d] = o1[d];
        }
        d0[20] = n0; d0[21] = 1.0f;
        d1[20] = n1; d1[21] = 1.0f;

    } else if (b < 336) {
        // ---- token MLP, 2 threads per token (80 blocks x 128 thr) ----
        float* Ws1 = sb;            // 4000
        float* Ws2 = sb + 4000;     // 800
        float* Wt1 = sb + 4800;     // 800
        float* Wt2 = sb + 5600;     // 800
        __shared__ float bs1[40], bs2[20], bt2s[20], tcs2[120];
        for (int i = tid; i < 4000; i += 128) Ws1[i] = Wseq1[i];
        for (int i = tid; i < 800; i += 128) { Ws2[i] = Wseq2[i]; Wt1[i] = Wto1[i]; Wt2[i] = Wto2[i]; }
        if (tid < 40) bs1[tid] = bseq1[tid];
        if (tid >= 64 && tid < 84) { bs2[tid - 64] = bseq2[tid - 64]; bt2s[tid - 64] = bto2[tid - 64]; }
        if (tid < 120) {
            int s = tid / 40, a = tid % 40;
            float acc = bto1[a];
            #pragma unroll
            for (int i = 0; i < 20; i++) acc += te[s * 20 + i] * Wto1[(20 + i) * 40 + a];
            tcs2[tid] = acc;
        }
        __syncthreads();

        int pid = (b - 256) * 128 + tid;
        int n = pid >> 1, h = pid & 1;
        int s = n / U_LEN, u = n % U_LEN;
        int hb = h * 20;

        float hs[20];
        #pragma unroll
        for (int a = 0; a < 20; a++) hs[a] = bs1[hb + a];

        float e[20];
        #pragma unroll 1
        for (int p = 0; p < 5; p++) {
            int k = 4 - p;
            int sel = (s < k) ? s : s - k;
            int xid = x[sel * U_LEN + u];
            const float4* vp = (const float4*)(vecs + (size_t)xid * 20);
            #pragma unroll
            for (int q = 0; q < 5; q++) {
                float4 f = vp[q];
                e[4*q] = f.x; e[4*q+1] = f.y; e[4*q+2] = f.z; e[4*q+3] = f.w;
            }
            #pragma unroll
            for (int i = 0; i < 20; i++) {
                float ei = e[i];
                #pragma unroll
                for (int a = 0; a < 20; a++) hs[a] += ei * Ws1[(p * 20 + i) * 40 + hb + a];
            }
        }

        float po[20];
        #pragma unroll
        for (int d = 0; d < 20; d++) po[d] = 0.0f;
        #pragma unroll 4
        for (int a = 0; a < 20; a++) {
            float r = fmaxf(hs[a], 0.0f);
            #pragma unroll
            for (int d = 0; d < 20; d++) po[d] += r * Ws2[(hb + a) * 20 + d];
        }

        int t24 = tslot[n] % 24;
        int seg = (t24 >= 22 || t24 < 6) ? 0 : (t24 < 14 ? 1 : 2);
        float ht[20];
        #pragma unroll
        for (int a = 0; a < 20; a++) ht[a] = tcs2[seg * 40 + hb + a];
        #pragma unroll
        for (int i = 0; i < 20; i++) {
            float ei = e[i];
            #pragma unroll
            for (int a = 0; a < 20; a++) ht[a] += ei * Wt1[i * 40 + hb + a];
        }
        float px[20];
        #pragma unroll
        for (int d = 0; d < 20; d++) px[d] = 0.0f;
        #pragma unroll 4
        for (int a = 0; a < 20; a++) {
            float r = fmaxf(ht[a], 0.0f);
            #pragma unroll
            for (int d = 0; d < 20; d++) px[d] += r * Wt2[(hb + a) * 20 + d];
        }

        float av[20];
        float nrm = 0.0f;
        #pragma unroll
        for (int d = 0; d < 20; d++) {
            float sp = po[d] + __shfl_xor_sync(0xffffffffu, po[d], 1);
            float tp = px[d] + __shfl_xor_sync(0xffffffffu, px[d], 1);
            av[d] = 0.5f * ((sp + bs2[d]) + (tp + bt2s[d]));
            nrm += av[d] * av[d];
        }
        float* dst = g_a + (size_t)n * VGS;
        #pragma unroll
        for (int d = 0; d < 10; d++) dst[hb / 2 + d] = av[hb / 2 + d];
        if (h == 0) { dst[20] = -0.5f; dst[21] = -0.5f * nrm; }

    } else {
        // ---- bucket + worklist ----
        __shared__ int scnt[NC];
        if (tid < NC) scnt[tid] = 0;
        __syncthreads();
        int xv[40];
        #pragma unroll
        for (int q = 0; q < 40; q++) xv[q] = x[tid + 128 * q];
        int cv[40];
        #pragma unroll
        for (int q = 0; q < 40; q++) cv[q] = Iarr[xv[q]];
        #pragma unroll
        for (int q = 0; q < 40; q++) {
            int c = cv[q];
            int p = atomicAdd(&scnt[c], 1);
            g_tok[c * NTOK + p] = tid + 128 * q;
        }
        __syncthreads();
        if (tid < NC) g_cnt[tid] = scnt[tid];
        if (tid == 0) {
            int w = 0;
            for (int c = 0; c < NC; c++) {
                int cnt = scnt[c];
                for (int st = 0; st < cnt; st += CHUNK) g_work[w++] = make_int2(c, st);
            }
            g_nwork = w;
        }
    }
}

// ============ K3: 16 tokens/block, 64 cands/lane, double-buffered row prefetch ============
__global__ void __launch_bounds__(256, 3)
k3_score(const int* __restrict__ x, const int* __restrict__ cand,
         const float* __restrict__ Eemb, float* __restrict__ out) {
    int bid = blockIdx.x;
    if (bid >= g_nwork) return;
    int2 wk = g_work[bid];
    int cid = wk.x, start = wk.y;
    int cnt = g_cnt[cid];
    int nIn = min(CHUNK, cnt - start);

    int tid = threadIdx.x, lane = tid & 31, warp = tid >> 5;

    __shared__ unsigned long long part[8][32][TOPK];
    __shared__ float sw_s[CHUNK][12];
    __shared__ int   si_s[CHUNK][12];
    __shared__ int   tok_s[CHUNK];

    if (tid < CHUNK) tok_s[tid] = g_tok[cid * NTOK + start + min(tid, nIn - 1)];
    __syncthreads();

    int tl = lane & 15;
    int half = lane >> 4;
    int token = tok_s[tl];

    const float* ap = g_a + (size_t)token * VGS;
    const ulonglong2* apv = (const ulonglong2*)ap;
    ulonglong2 A0 = apv[0], A1 = apv[1], A2 = apv[2], A3 = apv[3], A4 = apv[4];
    unsigned long long A5 = *(const unsigned long long*)(ap + 20);

    const float* vg = g_vg + (size_t)(cid * CANDN) * VGS;
    int j0 = warp * 128 + half * 64;

    float tv[TOPK]; int tj[TOPK];
    #pragma unroll
    for (int q = 0; q < TOPK; q++) { tv[q] = 3.4e38f; tj[q] = 0; }

    // prime the pipeline with row j0
    const float* vp = vg + (size_t)j0 * VGS;
    ulonglong2 q0 = ((const ulonglong2*)vp)[0];
    ulonglong2 q1 = ((const ulonglong2*)vp)[1];
    ulonglong2 q2 = ((const ulonglong2*)vp)[2];
    ulonglong2 q3 = ((const ulonglong2*)vp)[3];
    ulonglong2 q4 = ((const ulonglong2*)vp)[4];
    unsigned long long q5 = *(const unsigned long long*)(vp + 20);

    #pragma unroll 2
    for (int jj = 0; jj < 64; jj++) {
        // prefetch next row (unconditional; g_vg is padded one extra row)
        const float* np = vp + VGS;
        ulonglong2 n0 = ((const ulonglong2*)np)[0];
        ulonglong2 n1 = ((const ulonglong2*)np)[1];
        ulonglong2 n2 = ((const ulonglong2*)np)[2];
        ulonglong2 n3 = ((const ulonglong2*)np)[3];
        ulonglong2 n4 = ((const ulonglong2*)np)[4];
        unsigned long long n5 = *(const unsigned long long*)(np + 20);

        // compute on current row
        unsigned long long s0 = f2mul(q0.x, A0.x);
        unsigned long long s1 = f2mul(q0.y, A0.y);
        s0 = f2fma(q1.x, A1.x, s0);
        s1 = f2fma(q1.y, A1.y, s1);
        s0 = f2fma(q2.x, A2.x, s0);
        s1 = f2fma(q2.y, A2.y, s1);
        s0 = f2fma(q3.x, A3.x, s0);
        s1 = f2fma(q3.y, A3.y, s1);
        s0 = f2fma(q4.x, A4.x, s0);
        s1 = f2fma(q4.y, A4.y, s1);
        s0 = f2fma(q5, A5, s0);
        s0 = f2add(s0, s1);
        float lo = __uint_as_float((unsigned)(s0 & 0xffffffffull));
        float hi = __uint_as_float((unsigned)(s0 >> 32));
        float d2 = fmaxf(-2.0f * (lo + hi), 1e-12f);
        if (d2 < tv[TOPK - 1]) {
            float cv2 = d2; int cj = j0 + jj;
            #pragma unroll
            for (int q = 0; q < TOPK; q++) {
                bool p = cv2 < tv[q];
                float nv = p ? cv2 : tv[q];
                float xv = p ? tv[q] : cv2;
                int   nj = p ? cj : tj[q];
                int   xj = p ? tj[q] : cj;
                tv[q] = nv; tj[q] = nj; cv2 = xv; cj = xj;
            }
        }
        // rotate buffers
        q0 = n0; q1 = n1; q2 = n2; q3 = n3; q4 = n4; q5 = n5;
        vp = np;
    }
    #pragma unroll
    for (int q = 0; q < TOPK; q++)
        part[warp][lane][q] =
            ((unsigned long long)__float_as_uint(tv[q]) << 32) | (unsigned)tj[q];
    __syncthreads();

    // ---- 16-way streaming merge per token + softmax weights ----
    if (tid < nIn) {
        int t = tid;
        unsigned long long h[16];
        int p[16];
        #pragma unroll
        for (int w = 0; w < 8; w++) {
            h[w]     = part[w][t][0];      p[w] = 1;
            h[8 + w] = part[w][16 + t][0]; p[8 + w] = 1;
        }
        float ssum = 1.0f;
        #pragma unroll
        for (int k = 0; k < TOPK; k++) {
            unsigned long long best = h[0]; int bw = 0;
            #pragma unroll
            for (int l = 1; l < 16; l++) if (h[l] < best) { best = h[l]; bw = l; }
            #pragma unroll
            for (int l = 0; l < 16; l++) {
                if (bw == l) {
                    int tl2 = (l < 8) ? t : 16 + t;
                    int wq  = (l < 8) ? l : l - 8;
                    h[l] = (p[l] < TOPK) ? part[wq][tl2][p[l]] : 0xFFFFFFFFFFFFFFFFull;
                    p[l]++;
                }
            }
            float d2 = __uint_as_float((unsigned)(best >> 32));
            int   j  = (int)(best & 0xffffffffu);
            float sc = expf(-RHO_C * sqrtf(d2));
            float e  = expf(sc - 1.0f);
            ssum += e;
            sw_s[t][k] = e;
            si_s[t][k] = cand[cid * CANDN + j];
        }
        sw_s[t][TOPK] = 1.0f;
        si_s[t][TOPK] = x[tok_s[t]];
        float inv = 1.0f / ssum;
        #pragma unroll
        for (int k = 0; k < 11; k++) sw_s[t][k] *= inv;
    }
    __syncthreads();

    // ---- weighted embedding gather: 16 threads/token, 8 floats each ----
    int t  = tid >> 4;
    int pg = tid & 15;
    if (t < nIn) {
        int token2 = tok_s[t];
        float4 a0 = make_float4(0.f, 0.f, 0.f, 0.f), a1 = a0;
        #pragma unroll
        for (int k = 0; k < 11; k++) {
            float w = sw_s[t][k];
            const float4* ep = (const float4*)(Eemb + (size_t)si_s[t][k] * HD + pg * 8);
            float4 e0 = ep[0], e1 = ep[1];
            a0.x += w * e0.x; a0.y += w * e0.y; a0.z += w * e0.z; a0.w += w * e0.w;
            a1.x += w * e1.x; a1.y += w * e1.y; a1.z += w * e1.z; a1.w += w * e1.w;
        }
        float4* op = (float4*)(out + (size_t)token2 * HD + pg * 8);
        op[0] = a0; op[1] = a1;
    }
}

// ============ launch ============
extern "C" void kernel_launch(void* const* d_in, const int* in_sizes, int n_in,
                              void* d_out, int out_size) {
    const int*   x     = (const int*)  d_in[0];
    const int*   tslot = (const int*)  d_in[1];
    const float* vecs  = (const float*)d_in[2];
    const float* Eemb  = (const float*)d_in[3];
    const int*   Iarr  = (const int*)  d_in[4];
    const int*   cand  = (const int*)  d_in[5];
    const float* te    = (const float*)d_in[6];
    const float* Wseq1 = (const float*)d_in[7];
    const float* bseq1 = (const float*)d_in[8];
    const float* Wseq2 = (const float*)d_in[9];
    const float* bseq2 = (const float*)d_in[10];
    const float* Wto1  = (const float*)d_in[11];
    const float* bto1  = (const float*)d_in[12];
    const float* Wto2  = (const float*)d_in[13];
    const float* bto2  = (const float*)d_in[14];
    const float* Wti1  = (const float*)d_in[15];
    const float* bti1  = (const float*)d_in[16];
    const float* Wti2  = (const float*)d_in[17];
    const float* bti2  = (const float*)d_in[18];
    float* out = (float*)d_out;

    k_mid<<<337, 128>>>(x, tslot, vecs, cand, Iarr, te,
                        Wseq1, bseq1, Wseq2, bseq2,
                        Wto1, bto1, Wto2, bto2,
                        Wti1, bti1, Wti2, bti2);
    k3_score<<<NWORK_MAX, 256>>>(x, cand, Eemb, out);
}